// round 15
// baseline (speedup 1.0000x reference)
#include <cuda_runtime.h>
#include <cuda_bf16.h>
#include <stdint.h>

#define B     4
#define LQ    128
#define LK    1024
#define D     512
#define DV    512
#define UNITS 256
#define KCH   256          // k-chunk per fused-attn CTA
#define NCHMAX (LK / KCH)  // 4

typedef unsigned long long ull;

// Scratch (device globals — no allocation allowed)
__device__ float g_qp[B * LQ * UNITS];            // [b*LQ+q][u]
__device__ float g_kp[B * LK * UNITS];            // [b*LK+k][u]
__device__ float g_po[B][NCHMAX][LQ][DV];         // per-chunk partial outputs
__device__ float g_pm[B][NCHMAX][LQ][2];          // per-chunk (rowmax, rowsum)
__device__ int   g_vlen[B];

__device__ __forceinline__ float tanh_fast(float x) {
    float y;
    asm("tanh.approx.f32 %0, %1;" : "=f"(y) : "f"(x));
    return y;
}
__device__ __forceinline__ ull ffma2(ull a, ull b, ull c) {
    ull d;
    asm("fma.rn.f32x2 %0, %1, %2, %3;" : "=l"(d) : "l"(a), "l"(b), "l"(c));
    return d;
}
__device__ __forceinline__ ull dup2(float x) {
    ull r;
    asm("mov.b64 %0, {%1, %1};" : "=l"(r) : "f"(x));
    return r;
}
__device__ __forceinline__ float2 unpack2(ull v) {
    float2 f;
    asm("mov.b64 {%0, %1}, %2;" : "=f"(f.x), "=f"(f.y) : "l"(v));
    return f;
}
__device__ __forceinline__ uint32_t to_tf32(float x) {
    uint32_t r;
    asm("cvt.rna.tf32.f32 %0, %1;" : "=r"(r) : "f"(x));
    return r;
}
__device__ __forceinline__ void mma_tf32(
    float& d0, float& d1, float& d2, float& d3,
    uint32_t a0, uint32_t a1, uint32_t a2, uint32_t a3,
    uint32_t b0, uint32_t b1)
{
    asm("mma.sync.aligned.m16n8k8.row.col.f32.tf32.tf32.f32 "
        "{%0,%1,%2,%3}, {%4,%5,%6,%7}, {%8,%9}, {%0,%1,%2,%3};"
        : "+f"(d0), "+f"(d1), "+f"(d2), "+f"(d3)
        : "r"(a0), "r"(a1), "r"(a2), "r"(a3), "r"(b0), "r"(b1));
}

// ---------------------------------------------------------------------------
// 1) Projection GEMM via tf32 mma.sync (EXACT R11/R14 — best measured).
// ---------------------------------------------------------------------------
__global__ __launch_bounds__(256) void proj_kernel(
    const float* __restrict__ query, const float* __restrict__ key,
    const float* __restrict__ Wq,    const float* __restrict__ Wk,
    const void*  __restrict__ vl)
{
    const long long* l = (const long long*)vl;
    const int*       w = (const int*)vl;
    bool ok64 = true;
    #pragma unroll
    for (int i = 0; i < B; i++) {
        long long x = l[i];
        if (x < 1 || x > LK) ok64 = false;
    }
    if (blockIdx.x == 0 && blockIdx.y == 0 && threadIdx.x == 0) {
        #pragma unroll
        for (int i = 0; i < B; i++) g_vlen[i] = ok64 ? (int)l[i] : w[i];
    }

    int mg = blockIdx.x * 64;
    int n0 = blockIdx.y * 64;
    bool is_q = (mg < B * LQ);

    const float *X, *W;
    float* Y;
    int m0;
    if (is_q) { X = query; W = Wq; Y = g_qp; m0 = mg; }
    else {
        m0 = mg - B * LQ;
        int bb = m0 >> 10;
        int krow = m0 & 1023;
        int vb = ok64 ? (int)l[bb] : w[bb];
        if (krow >= vb) return;          // tile fully masked downstream
        X = key; W = Wk; Y = g_kp;
    }

    __shared__ uint4 Af[2][16][32];
    __shared__ uint2 Bf[2][32][32];

    int tid  = threadIdx.x;
    int lane = tid & 31;
    int wf   = tid >> 5;
    int warpM = wf >> 2;
    int warpN = wf & 3;
    int g  = lane >> 2;
    int t4 = lane & 3;

    float ar[2][4], br[4][2];

    auto ldg_tile = [&](int kt) {
        #pragma unroll
        for (int j = 0; j < 2; j++) {
            int fragIdx = wf + 8 * j;
            int c = fragIdx >> 2, f = fragIdx & 3;
            const float* p = X + (size_t)(m0 + f * 16 + g) * D + kt * 32 + c * 8 + t4;
            ar[j][0] = p[0];
            ar[j][1] = p[8 * D];
            ar[j][2] = p[4];
            ar[j][3] = p[8 * D + 4];
        }
        #pragma unroll
        for (int j = 0; j < 4; j++) {
            int fragIdx = wf + 8 * j;
            int c = fragIdx >> 3, s8 = fragIdx & 7;
            const float* p = W + (size_t)(n0 + s8 * 8 + g) * D + kt * 32 + c * 8 + t4;
            br[j][0] = p[0];
            br[j][1] = p[4];
        }
    };
    auto sts_tile = [&](int buf) {
        #pragma unroll
        for (int j = 0; j < 2; j++) {
            int fragIdx = wf + 8 * j;
            Af[buf][fragIdx][lane] = make_uint4(
                to_tf32(ar[j][0]), to_tf32(ar[j][1]),
                to_tf32(ar[j][2]), to_tf32(ar[j][3]));
        }
        #pragma unroll
        for (int j = 0; j < 4; j++) {
            int fragIdx = wf + 8 * j;
            Bf[buf][fragIdx][lane] = make_uint2(to_tf32(br[j][0]), to_tf32(br[j][1]));
        }
    };

    ldg_tile(0);
    sts_tile(0);
    __syncthreads();

    float acc[2][2][4] = {};

    const int NT = D / 32;
    for (int t = 0; t < NT; t++) {
        int buf = t & 1;
        if (t + 1 < NT) ldg_tile(t + 1);

        #pragma unroll
        for (int c = 0; c < 4; c++) {
            uint4 afr[2];
            uint2 bfr[2];
            #pragma unroll
            for (int fi = 0; fi < 2; fi++)
                afr[fi] = Af[buf][c * 4 + warpM * 2 + fi][lane];
            #pragma unroll
            for (int ni = 0; ni < 2; ni++)
                bfr[ni] = Bf[buf][c * 8 + warpN * 2 + ni][lane];
            #pragma unroll
            for (int fi = 0; fi < 2; fi++)
                #pragma unroll
                for (int ni = 0; ni < 2; ni++)
                    mma_tf32(acc[fi][ni][0], acc[fi][ni][1],
                             acc[fi][ni][2], acc[fi][ni][3],
                             afr[fi].x, afr[fi].y, afr[fi].z, afr[fi].w,
                             bfr[ni].x, bfr[ni].y);
        }

        if (t + 1 < NT) sts_tile(buf ^ 1);
        __syncthreads();
    }

    #pragma unroll
    for (int fi = 0; fi < 2; fi++) {
        #pragma unroll
        for (int ni = 0; ni < 2; ni++) {
            int row = m0 + warpM * 32 + fi * 16 + g;
            int col = n0 + warpN * 16 + ni * 8 + 2 * t4;
            *(float2*)(Y + (size_t)row * UNITS + col) =
                make_float2(acc[fi][ni][0], acc[fi][ni][1]);
            *(float2*)(Y + (size_t)(row + 8) * UNITS + col) =
                make_float2(acc[fi][ni][2], acc[fi][ni][3]);
        }
    }
}

// ---------------------------------------------------------------------------
// 2) Fused attention chunk: scores -> smem, chunk softmax partials,
//    partial GEMM exp(s-m) @ V. Grid (4, 16, B) = 256 CTAs, 256 thr.
//    sT padded to 12 floats/row: 16B-aligned rows for LDS.128 row-pairs.
// ---------------------------------------------------------------------------
__global__ __launch_bounds__(256) void attn_kernel(
    const float* __restrict__ vvec, const float* __restrict__ value)
{
    int b    = blockIdx.z;
    int q0   = blockIdx.y * 8;
    int ch   = blockIdx.x;
    int k0   = ch * KCH;
    int vlen = g_vlen[b];
    if (k0 >= vlen) return;             // uniform exit before any barrier
    int len  = min(KCH, vlen - k0);

    __shared__ float sT[KCH][12];       // [k][row(8) + pad]
    __shared__ float sm[8], ss[8];

    int tid  = threadIdx.x;
    int lane = tid & 31;
    int wid  = tid >> 5;

    // ---------------- phase 1: raw scores into sT ----------------
    float vr[8];
    {
        float4 a = *(const float4*)(vvec + lane * 8);
        float4 c = *(const float4*)(vvec + lane * 8 + 4);
        vr[0] = a.x; vr[1] = a.y; vr[2] = a.z; vr[3] = a.w;
        vr[4] = c.x; vr[5] = c.y; vr[6] = c.z; vr[7] = c.w;
    }
    float qv[8][8];
    #pragma unroll
    for (int qq = 0; qq < 8; qq++) {
        const float* qr = g_qp + (size_t)(b * LQ + q0 + qq) * UNITS + lane * 8;
        float4 a = *(const float4*)qr;
        float4 c = *(const float4*)(qr + 4);
        qv[qq][0] = a.x; qv[qq][1] = a.y; qv[qq][2] = a.z; qv[qq][3] = a.w;
        qv[qq][4] = c.x; qv[qq][5] = c.y; qv[qq][6] = c.z; qv[qq][7] = c.w;
    }

    const float* kpb = g_kp + (size_t)b * LK * UNITS;
    int qq_out = 4 * ((lane >> 2) & 1) + 2 * ((lane >> 3) & 1) + ((lane >> 4) & 1);
    bool writer = (lane & 3) == 0;

    int kend = k0 + len;
    int k = k0 + wid;

    float4 ka, kb;
    if (k < kend) {
        const float* kr = kpb + (size_t)k * UNITS + lane * 8;
        ka = *(const float4*)kr;
        kb = *(const float4*)(kr + 4);
    }

    while (k < kend) {
        int kn = k + 8;
        float4 kan, kbn;
        if (kn < kend) {
            const float* krn = kpb + (size_t)kn * UNITS + lane * 8;
            kan = *(const float4*)krn;
            kbn = *(const float4*)(krn + 4);
        }

        float kv[8] = {ka.x, ka.y, ka.z, ka.w, kb.x, kb.y, kb.z, kb.w};
        float s[8] = {0.f, 0.f, 0.f, 0.f, 0.f, 0.f, 0.f, 0.f};
        #pragma unroll
        for (int j = 0; j < 8; j++) {
            float kj = kv[j];
            float vj = vr[j];
            #pragma unroll
            for (int qq = 0; qq < 8; qq++)
                s[qq] = fmaf(vj, tanh_fast(qv[qq][j] + kj), s[qq]);
        }

        #define FOLD(dst, a0_, b0_, m)                                   \
            {                                                            \
                float x_ = (lane & (m)) ? (b0_) : (a0_);                 \
                float y_ = (lane & (m)) ? (a0_) : (b0_);                 \
                dst = x_ + __shfl_xor_sync(0xFFFFFFFFu, y_, (m));        \
            }
        float t0, t1, t2, t3, u0, u1, v;
        FOLD(t0, s[0], s[1], 16)
        FOLD(t1, s[2], s[3], 16)
        FOLD(t2, s[4], s[5], 16)
        FOLD(t3, s[6], s[7], 16)
        FOLD(u0, t0, t1, 8)
        FOLD(u1, t2, t3, 8)
        FOLD(v,  u0, u1, 4)
        v += __shfl_xor_sync(0xFFFFFFFFu, v, 2);
        v += __shfl_xor_sync(0xFFFFFFFFu, v, 1);
        #undef FOLD

        if (writer) sT[k - k0][qq_out] = v;

        ka = kan; kb = kbn;
        k = kn;
    }
    __syncthreads();

    // ---------------- phase 2: per-row chunk max/sum, exp in place -------
    {
        int r = wid;                     // warp per row
        float m = -3.0e38f;
        for (int kk = lane; kk < len; kk += 32) m = fmaxf(m, sT[kk][r]);
        #pragma unroll
        for (int off = 16; off > 0; off >>= 1)
            m = fmaxf(m, __shfl_xor_sync(0xFFFFFFFFu, m, off));
        float sum = 0.f;
        for (int kk = lane; kk < len; kk += 32) sum += __expf(sT[kk][r] - m);
        #pragma unroll
        for (int off = 16; off > 0; off >>= 1)
            sum += __shfl_xor_sync(0xFFFFFFFFu, sum, off);
        if (lane == 0) { sm[r] = m; ss[r] = sum; }
    }
    __syncthreads();

    {
        int kk = tid;                    // 256 threads cover KCH rows of sT
        if (kk < len) {
            #pragma unroll
            for (int r = 0; r < 8; r++)
                sT[kk][r] = __expf(sT[kk][r] - sm[r]);
        } else {
            #pragma unroll
            for (int r = 0; r < 8; r++)
                sT[kk][r] = 0.f;
        }
    }
    __syncthreads();

    // ---------------- phase 3: partial GEMM p @ V -------------------------
    // thread owns cols (c0, c0+1); acc[i] = rows (2i, 2i+1) packed f32x2.
    const float* V = value + (size_t)b * LK * DV + (size_t)k0 * DV;
    int c0 = 2 * tid;

    ull acc[4][2] = {};
    int kcend = (len + 3) & ~3;

    for (int kk = 0; kk < kcend; kk += 4) {
        float2 vk[4];
        #pragma unroll
        for (int j = 0; j < 4; j++)
            vk[j] = *(const float2*)(V + (size_t)(kk + j) * DV + c0);
        #pragma unroll
        for (int j = 0; j < 4; j++) {
            uint4 p0 = *(const uint4*)&sT[kk + j][0];  // rows 0-3
            uint4 p1 = *(const uint4*)&sT[kk + j][4];  // rows 4-7
            ull pp[4];
            pp[0] = ((ull)p0.y << 32) | p0.x;
            pp[1] = ((ull)p0.w << 32) | p0.z;
            pp[2] = ((ull)p1.y << 32) | p1.x;
            pp[3] = ((ull)p1.w << 32) | p1.z;
            ull dv0 = dup2(vk[j].x);
            ull dv1 = dup2(vk[j].y);
            #pragma unroll
            for (int i = 0; i < 4; i++) {
                acc[i][0] = ffma2(pp[i], dv0, acc[i][0]);
                acc[i][1] = ffma2(pp[i], dv1, acc[i][1]);
            }
        }
    }

    // write partials
    float* po = &g_po[b][ch][q0][0];
    #pragma unroll
    for (int i = 0; i < 4; i++) {
        float2 a0 = unpack2(acc[i][0]);   // (row2i,c0), (row2i+1,c0)
        float2 a1 = unpack2(acc[i][1]);   // (row2i,c0+1), (row2i+1,c0+1)
        *(float2*)(po + (size_t)(2 * i)     * DV + c0) = make_float2(a0.x, a1.x);
        *(float2*)(po + (size_t)(2 * i + 1) * DV + c0) = make_float2(a0.y, a1.y);
    }
    if (tid < 8) {
        g_pm[b][ch][q0 + tid][0] = sm[tid];
        g_pm[b][ch][q0 + tid][1] = ss[tid];
    }
}

// ---------------------------------------------------------------------------
// 3) Combine partial chunks: out = (Σ_c po_c * exp(m_c - M)) / Σ_c s_c*exp(..)
//    Grid (16, B) = 64 CTAs, 256 thr (thread owns 2 cols x 8 rows).
// ---------------------------------------------------------------------------
__global__ __launch_bounds__(256) void combine_kernel(float* __restrict__ out)
{
    int q0 = blockIdx.x * 8;
    int b  = blockIdx.y;
    int vlen = g_vlen[b];
    int nc = (vlen + KCH - 1) / KCH;

    __shared__ float f[NCHMAX][8];
    __shared__ float rinv[8];

    int tid = threadIdx.x;
    if (tid < 8) {
        int r = tid;
        float M = -3.0e38f;
        for (int c = 0; c < nc; c++)
            M = fmaxf(M, g_pm[b][c][q0 + r][0]);
        float S = 0.f;
        for (int c = 0; c < nc; c++) {
            float fc = __expf(g_pm[b][c][q0 + r][0] - M);
            S += g_pm[b][c][q0 + r][1] * fc;
            f[c][r] = fc;
        }
        rinv[r] = 1.0f / S;
    }
    __syncthreads();

    int c0 = 2 * tid;
    #pragma unroll
    for (int r = 0; r < 8; r++) {
        float ox = 0.f, oy = 0.f;
        for (int c = 0; c < nc; c++) {
            float2 p = *(const float2*)&g_po[b][c][q0 + r][c0];
            float fc = f[c][r];
            ox = fmaf(p.x, fc, ox);
            oy = fmaf(p.y, fc, oy);
        }
        float iv = rinv[r];
        *(float2*)(out + (size_t)(b * LQ + q0 + r) * DV + c0) =
            make_float2(ox * iv, oy * iv);
    }
}

// ---------------------------------------------------------------------------
// kernel_launch — inputs: query, key, value, valid_len, W_q, W_k, v
// ---------------------------------------------------------------------------
extern "C" void kernel_launch(void* const* d_in, const int* in_sizes, int n_in,
                              void* d_out, int out_size)
{
    const float* query = (const float*)d_in[0];
    const float* key   = (const float*)d_in[1];
    const float* value = (const float*)d_in[2];
    const void*  vlen  = d_in[3];
    const float* W_q   = (const float*)d_in[4];
    const float* W_k   = (const float*)d_in[5];
    const float* vvec  = (const float*)d_in[6];
    float* out = (float*)d_out;

    // 1) fused q+k projection via tf32 mma: 72 x 4 = 288 CTAs, 256 thr
    proj_kernel<<<dim3((B * LQ + B * LK) / 64, UNITS / 64), 256>>>(
        query, key, W_q, W_k, vlen);

    // 2) fused scores+softmax+partial-output: (4,16,4) = 256 CTAs
    attn_kernel<<<dim3(LK / KCH, LQ / 8, B), 256>>>(vvec, value);

    // 3) combine chunk partials: (16,4) = 64 CTAs
    combine_kernel<<<dim3(LQ / 8, B), 256>>>(out);
}

// round 16
// speedup vs baseline: 1.5000x; 1.5000x over previous
#include <cuda_runtime.h>
#include <cuda_bf16.h>
#include <stdint.h>

#define B     4
#define LQ    128
#define LK    1024
#define D     512
#define DV    512
#define UNITS 256

typedef unsigned long long ull;

// Scratch (device globals — no allocation allowed)
__device__ float g_qp[B * LQ * UNITS];         // [b*LQ+q][u]
__device__ float g_kp[B * LK * UNITS];         // [b*LK+k][u]
__device__ float g_sc[B * LQ * LK];            // raw scores (unmasked region)
__device__ int   g_vlen[B];

__device__ __forceinline__ float tanh_fast(float x) {
    float y;
    asm("tanh.approx.f32 %0, %1;" : "=f"(y) : "f"(x));
    return y;
}
__device__ __forceinline__ ull ffma2(ull a, ull b, ull c) {
    ull d;
    asm("fma.rn.f32x2 %0, %1, %2, %3;" : "=l"(d) : "l"(a), "l"(b), "l"(c));
    return d;
}
__device__ __forceinline__ ull dup2(float x) {
    ull r;
    asm("mov.b64 %0, {%1, %1};" : "=l"(r) : "f"(x));
    return r;
}
__device__ __forceinline__ float2 unpack2(ull v) {
    float2 f;
    asm("mov.b64 {%0, %1}, %2;" : "=f"(f.x), "=f"(f.y) : "l"(v));
    return f;
}
__device__ __forceinline__ uint32_t to_tf32(float x) {
    uint32_t r;
    asm("cvt.rna.tf32.f32 %0, %1;" : "=r"(r) : "f"(x));
    return r;
}
__device__ __forceinline__ void mma_tf32(
    float& d0, float& d1, float& d2, float& d3,
    uint32_t a0, uint32_t a1, uint32_t a2, uint32_t a3,
    uint32_t b0, uint32_t b1)
{
    asm("mma.sync.aligned.m16n8k8.row.col.f32.tf32.tf32.f32 "
        "{%0,%1,%2,%3}, {%4,%5,%6,%7}, {%8,%9}, {%0,%1,%2,%3};"
        : "+f"(d0), "+f"(d1), "+f"(d2), "+f"(d3)
        : "r"(a0), "r"(a1), "r"(a2), "r"(a3), "r"(b0), "r"(b1));
}

#define CP16(dst_u32, src_ptr) \
    asm volatile("cp.async.ca.shared.global [%0], [%1], 16;" \
                 :: "r"(dst_u32), "l"(src_ptr))
#define CP_COMMIT()  asm volatile("cp.async.commit_group;")
#define CP_WAIT2()   asm volatile("cp.async.wait_group 2;")

// proj smem geometry: 4 stages x 2 operands x [64 rows][36 floats (pad)]
#define PROJ_PAD   36
#define PROJ_STAGE (64 * PROJ_PAD)                 // floats per operand-stage
#define PROJ_SMEM_BYTES (4 * 2 * PROJ_STAGE * 4)   // 73728

// ---------------------------------------------------------------------------
// 1) Projection GEMM via tf32 mma.sync + cp.async 4-stage pipeline.
//    rows [0,512): g_qp ; rows [512,4608): g_kp (masked k-tiles exit).
//    CTA 64m x 64n, BK=32, 256 thr = 8 warps (2m x 4n), warp tile 32x16.
//    Natural [row][k] smem (pad 36 -> conflict-free fragment LDS), one
//    barrier per tile, wait_group 2 => >= 2 tiles of latency cover.
// ---------------------------------------------------------------------------
__global__ __launch_bounds__(256) void proj_kernel(
    const float* __restrict__ query, const float* __restrict__ key,
    const float* __restrict__ Wq,    const float* __restrict__ Wk,
    const void*  __restrict__ vl)
{
    const long long* l = (const long long*)vl;
    const int*       w = (const int*)vl;
    bool ok64 = true;
    #pragma unroll
    for (int i = 0; i < B; i++) {
        long long x = l[i];
        if (x < 1 || x > LK) ok64 = false;
    }
    if (blockIdx.x == 0 && blockIdx.y == 0 && threadIdx.x == 0) {
        #pragma unroll
        for (int i = 0; i < B; i++) g_vlen[i] = ok64 ? (int)l[i] : w[i];
    }

    int mg = blockIdx.x * 64;
    int n0 = blockIdx.y * 64;
    bool is_q = (mg < B * LQ);

    const float *X, *W;
    float* Y;
    int m0;
    if (is_q) { X = query; W = Wq; Y = g_qp; m0 = mg; }
    else {
        m0 = mg - B * LQ;
        int bb = m0 >> 10;
        int krow = m0 & 1023;
        int vb = ok64 ? (int)l[bb] : w[bb];
        if (krow >= vb) return;          // tile fully masked downstream
        X = key; W = Wk; Y = g_kp;
    }

    extern __shared__ float smem[];
    float* Xs = smem;                    // [4][64][36]
    float* Ws = smem + 4 * PROJ_STAGE;   // [4][64][36]

    int tid  = threadIdx.x;
    int lane = tid & 31;
    int wf   = tid >> 5;
    int warpM = wf >> 2;                 // 0..1
    int warpN = wf & 3;                  // 0..3
    int g  = lane >> 2;                  // 0..7
    int t4 = lane & 3;                   // 0..3

    // cp.async chunk mapping: 512 16B-chunks per operand per tile,
    // 2 chunks/thread: c = tid, tid+256; row = c>>3, kq = (c&7)*4 floats.
    int c1 = tid, c2 = tid + 256;
    int r1 = c1 >> 3, kq1 = (c1 & 7) * 4;
    int r2 = c2 >> 3, kq2 = (c2 & 7) * 4;

    uint32_t xs_base = (uint32_t)__cvta_generic_to_shared(Xs);
    uint32_t ws_base = (uint32_t)__cvta_generic_to_shared(Ws);

    auto issue_tile = [&](int kt, int st) {
        uint32_t xb = xs_base + (uint32_t)(st * PROJ_STAGE) * 4;
        uint32_t wb = ws_base + (uint32_t)(st * PROJ_STAGE) * 4;
        CP16(xb + (uint32_t)(r1 * PROJ_PAD + kq1) * 4,
             X + (size_t)(m0 + r1) * D + kt * 32 + kq1);
        CP16(xb + (uint32_t)(r2 * PROJ_PAD + kq2) * 4,
             X + (size_t)(m0 + r2) * D + kt * 32 + kq2);
        CP16(wb + (uint32_t)(r1 * PROJ_PAD + kq1) * 4,
             W + (size_t)(n0 + r1) * D + kt * 32 + kq1);
        CP16(wb + (uint32_t)(r2 * PROJ_PAD + kq2) * 4,
             W + (size_t)(n0 + r2) * D + kt * 32 + kq2);
    };

    const int NT = D / 32;               // 16 tiles
    issue_tile(0, 0); CP_COMMIT();
    issue_tile(1, 1); CP_COMMIT();
    issue_tile(2, 2); CP_COMMIT();

    float acc[2][2][4] = {};             // [fi][ni][4]

    int rb0 = warpM * 32;                // warp m-base
    int cb0 = warpN * 16;                // warp n-base

    for (int t = 0; t < NT; t++) {
        CP_WAIT2();                      // tile t landed (<=2 groups pending)
        __syncthreads();

        const float* xst = Xs + (t & 3) * PROJ_STAGE;
        const float* wst = Ws + (t & 3) * PROJ_STAGE;

        #pragma unroll
        for (int c = 0; c < 4; c++) {
            int kc = c * 8;
            uint32_t a[2][4], bfr[2][2];
            #pragma unroll
            for (int fi = 0; fi < 2; fi++) {
                int rb = rb0 + fi * 16;
                a[fi][0] = to_tf32(xst[(rb + g)     * PROJ_PAD + kc + t4]);
                a[fi][1] = to_tf32(xst[(rb + g + 8) * PROJ_PAD + kc + t4]);
                a[fi][2] = to_tf32(xst[(rb + g)     * PROJ_PAD + kc + t4 + 4]);
                a[fi][3] = to_tf32(xst[(rb + g + 8) * PROJ_PAD + kc + t4 + 4]);
            }
            #pragma unroll
            for (int ni = 0; ni < 2; ni++) {
                int cb = cb0 + ni * 8 + g;
                bfr[ni][0] = to_tf32(wst[cb * PROJ_PAD + kc + t4]);
                bfr[ni][1] = to_tf32(wst[cb * PROJ_PAD + kc + t4 + 4]);
            }
            #pragma unroll
            for (int fi = 0; fi < 2; fi++)
                #pragma unroll
                for (int ni = 0; ni < 2; ni++)
                    mma_tf32(acc[fi][ni][0], acc[fi][ni][1],
                             acc[fi][ni][2], acc[fi][ni][3],
                             a[fi][0], a[fi][1], a[fi][2], a[fi][3],
                             bfr[ni][0], bfr[ni][1]);
        }

        // safe: stage (t+3)&3 held tile t-1, all warps done with it before
        // this iteration's barrier. Empty commits keep group counting fixed.
        if (t + 3 < NT) issue_tile(t + 3, (t + 3) & 3);
        CP_COMMIT();
    }

    // epilogue: c0=(g,2t4) c1=(g,2t4+1) c2=(g+8,2t4) c3=(g+8,2t4+1)
    #pragma unroll
    for (int fi = 0; fi < 2; fi++) {
        #pragma unroll
        for (int ni = 0; ni < 2; ni++) {
            int row = m0 + rb0 + fi * 16 + g;
            int col = n0 + cb0 + ni * 8 + 2 * t4;
            *(float2*)(Y + (size_t)row * UNITS + col) =
                make_float2(acc[fi][ni][0], acc[fi][ni][1]);
            *(float2*)(Y + (size_t)(row + 8) * UNITS + col) =
                make_float2(acc[fi][ni][2], acc[fi][ni][3]);
        }
    }
}

// ---------------------------------------------------------------------------
// 2) Scores (EXACT R14 config — reconfirmed best): warp per k, 8 q-rows,
//    prefetch + butterfly reduce, k-tile 32, grid (32,16,4) = 2048 CTAs.
// ---------------------------------------------------------------------------
__global__ __launch_bounds__(256) void score_kernel(const float* __restrict__ vvec)
{
    int b    = blockIdx.z;
    int q0   = blockIdx.y * 8;
    int k0   = blockIdx.x * 32;
    int vlen = g_vlen[b];
    if (k0 >= vlen) return;
    int kmax = min(k0 + 32, vlen);

    int lane = threadIdx.x & 31;
    int wid  = threadIdx.x >> 5;

    int k = k0 + wid;
    if (k >= kmax) return;

    float vr[8];
    {
        float4 a = *(const float4*)(vvec + lane * 8);
        float4 c = *(const float4*)(vvec + lane * 8 + 4);
        vr[0] = a.x; vr[1] = a.y; vr[2] = a.z; vr[3] = a.w;
        vr[4] = c.x; vr[5] = c.y; vr[6] = c.z; vr[7] = c.w;
    }
    float qv[8][8];
    #pragma unroll
    for (int qq = 0; qq < 8; qq++) {
        const float* qr = g_qp + (size_t)(b * LQ + q0 + qq) * UNITS + lane * 8;
        float4 a = *(const float4*)qr;
        float4 c = *(const float4*)(qr + 4);
        qv[qq][0] = a.x; qv[qq][1] = a.y; qv[qq][2] = a.z; qv[qq][3] = a.w;
        qv[qq][4] = c.x; qv[qq][5] = c.y; qv[qq][6] = c.z; qv[qq][7] = c.w;
    }

    const float* kpb = g_kp + (size_t)b * LK * UNITS;
    float*       scb = g_sc + (size_t)(b * LQ + q0) * LK;

    int qq_out = 4 * ((lane >> 2) & 1) + 2 * ((lane >> 3) & 1) + ((lane >> 4) & 1);
    bool writer = (lane & 3) == 0;
    float* wptr = scb + (size_t)qq_out * LK;

    float4 ka, kb;
    {
        const float* kr = kpb + (size_t)k * UNITS + lane * 8;
        ka = *(const float4*)kr;
        kb = *(const float4*)(kr + 4);
    }

    while (k < kmax) {
        int kn = k + 8;
        float4 kan, kbn;
        if (kn < kmax) {
            const float* krn = kpb + (size_t)kn * UNITS + lane * 8;
            kan = *(const float4*)krn;
            kbn = *(const float4*)(krn + 4);
        }

        float kv[8] = {ka.x, ka.y, ka.z, ka.w, kb.x, kb.y, kb.z, kb.w};
        float s[8] = {0.f, 0.f, 0.f, 0.f, 0.f, 0.f, 0.f, 0.f};
        #pragma unroll
        for (int j = 0; j < 8; j++) {
            float kj = kv[j];
            float vj = vr[j];
            #pragma unroll
            for (int qq = 0; qq < 8; qq++)
                s[qq] = fmaf(vj, tanh_fast(qv[qq][j] + kj), s[qq]);
        }

        #define FOLD(dst, a0_, b0_, m)                                   \
            {                                                            \
                float x_ = (lane & (m)) ? (b0_) : (a0_);                 \
                float y_ = (lane & (m)) ? (a0_) : (b0_);                 \
                dst = x_ + __shfl_xor_sync(0xFFFFFFFFu, y_, (m));        \
            }
        float t0, t1, t2, t3, u0, u1, v;
        FOLD(t0, s[0], s[1], 16)
        FOLD(t1, s[2], s[3], 16)
        FOLD(t2, s[4], s[5], 16)
        FOLD(t3, s[6], s[7], 16)
        FOLD(u0, t0, t1, 8)
        FOLD(u1, t2, t3, 8)
        FOLD(v,  u0, u1, 4)
        v += __shfl_xor_sync(0xFFFFFFFFu, v, 2);
        v += __shfl_xor_sync(0xFFFFFFFFu, v, 1);
        #undef FOLD

        if (writer) wptr[k] = v;

        ka = kan; kb = kbn;
        k = kn;
    }
}

// ---------------------------------------------------------------------------
// 3) Fused softmax + output GEMM (EXACT R14).
// ---------------------------------------------------------------------------
__global__ __launch_bounds__(256) void out_kernel(
    const float* __restrict__ value, float* __restrict__ out)
{
    __shared__ float As[32][34];
    __shared__ float Bs[32][64];
    __shared__ float rmax[32], rinv[32];

    int b    = blockIdx.z;
    int m0   = blockIdx.x * 32;
    int n0   = blockIdx.y * 64;
    int vlen = g_vlen[b];
    int kend = (vlen + 31) & ~31;

    const float* S = g_sc  + (size_t)(b * LQ + m0) * LK;
    const float* V = value + (size_t)b * LK * DV;

    int tid  = threadIdx.x;
    int lane = tid & 31;
    int wid  = tid >> 5;

    for (int r = wid; r < 32; r += 8) {
        const float* srow = S + (size_t)r * LK;
        float m = -3.0e38f;
        for (int k = lane; k < vlen; k += 32) m = fmaxf(m, srow[k]);
        #pragma unroll
        for (int off = 16; off > 0; off >>= 1)
            m = fmaxf(m, __shfl_xor_sync(0xFFFFFFFFu, m, off));
        float s = 0.f;
        for (int k = lane; k < vlen; k += 32) s += __expf(srow[k] - m);
        #pragma unroll
        for (int off = 16; off > 0; off >>= 1)
            s += __shfl_xor_sync(0xFFFFFFFFu, s, off);
        if (lane == 0) { rmax[r] = m; rinv[r] = 1.0f / s; }
    }
    __syncthreads();

    int ty = tid >> 4, tx = tid & 15;
    int am = tid >> 3, ak = (tid & 7) * 4;
    int bk = tid >> 3, bn = (tid & 7) * 8;

    ull acc[2][2] = {};

    for (int k0 = 0; k0 < kend; k0 += 32) {
        float4 sv = *(const float4*)(S + (size_t)am * LK + k0 + ak);
        float mr = rmax[am];
        int kg = k0 + ak;
        As[ak + 0][am] = (kg + 0 < vlen) ? __expf(sv.x - mr) : 0.f;
        As[ak + 1][am] = (kg + 1 < vlen) ? __expf(sv.y - mr) : 0.f;
        As[ak + 2][am] = (kg + 2 < vlen) ? __expf(sv.z - mr) : 0.f;
        As[ak + 3][am] = (kg + 3 < vlen) ? __expf(sv.w - mr) : 0.f;

        const float* vp = V + (size_t)(k0 + bk) * DV + n0 + bn;
        *(float4*)&Bs[bk][bn]     = *(const float4*)(vp);
        *(float4*)&Bs[bk][bn + 4] = *(const float4*)(vp + 4);
        __syncthreads();

        #pragma unroll
        for (int kk = 0; kk < 32; kk++) {
            float2 af = *(const float2*)&As[kk][ty * 2];
            ull ap0 = dup2(af.x);
            ull ap1 = dup2(af.y);
            longlong2 bv = *(const longlong2*)&Bs[kk][tx * 4];
            acc[0][0] = ffma2(ap0, (ull)bv.x, acc[0][0]);
            acc[0][1] = ffma2(ap0, (ull)bv.y, acc[0][1]);
            acc[1][0] = ffma2(ap1, (ull)bv.x, acc[1][0]);
            acc[1][1] = ffma2(ap1, (ull)bv.y, acc[1][1]);
        }
        __syncthreads();
    }

    #pragma unroll
    for (int i = 0; i < 2; i++) {
        int r = ty * 2 + i;
        float inv = rinv[r];
        float2 r0 = unpack2(acc[i][0]);
        float2 r1 = unpack2(acc[i][1]);
        *(float4*)(out + (size_t)(b * LQ + m0 + r) * DV + n0 + tx * 4) =
            make_float4(r0.x * inv, r0.y * inv, r1.x * inv, r1.y * inv);
    }
}

// ---------------------------------------------------------------------------
// kernel_launch — inputs: query, key, value, valid_len, W_q, W_k, v
// ---------------------------------------------------------------------------
extern "C" void kernel_launch(void* const* d_in, const int* in_sizes, int n_in,
                              void* d_out, int out_size)
{
    const float* query = (const float*)d_in[0];
    const float* key   = (const float*)d_in[1];
    const float* value = (const float*)d_in[2];
    const void*  vlen  = d_in[3];
    const float* W_q   = (const float*)d_in[4];
    const float* W_k   = (const float*)d_in[5];
    const float* vvec  = (const float*)d_in[6];
    float* out = (float*)d_out;

    // allow 72KB dynamic smem (host attr call; idempotent, not a stream op)
    cudaFuncSetAttribute(proj_kernel,
                         cudaFuncAttributeMaxDynamicSharedMemorySize,
                         PROJ_SMEM_BYTES);

    // 1) fused q+k projection via tf32 mma + cp.async: 72 x 4 = 288 CTAs
    proj_kernel<<<dim3((B * LQ + B * LK) / 64, UNITS / 64), 256,
                  PROJ_SMEM_BYTES>>>(query, key, W_q, W_k, vlen);

    // 2) scores: 32 x 16 x 4 = 2048 CTAs, 256 thr (masked tiles exit)
    score_kernel<<<dim3(LK / 32, LQ / 8, B), 256>>>(vvec);

    // 3) fused softmax + output GEMM: 4 x 8 x 4 = 128 CTAs
    out_kernel<<<dim3(LQ / 32, DV / 64, B), 256>>>(value, out);
}

// round 17
// speedup vs baseline: 1.5031x; 1.0021x over previous
#include <cuda_runtime.h>
#include <cuda_bf16.h>
#include <stdint.h>

#define B     4
#define LQ    128
#define LK    1024
#define D     512
#define DV    512
#define UNITS 256

typedef unsigned long long ull;

// Scratch (device globals — no allocation allowed)
__device__ float g_qp[B * LQ * UNITS];         // [b*LQ+q][u]
__device__ float g_kp[B * LK * UNITS];         // [b*LK+k][u]
__device__ float g_sc[B * LQ * LK];            // raw scores (unmasked region)
__device__ int   g_vlen[B];

__device__ __forceinline__ float tanh_fast(float x) {
    float y;
    asm("tanh.approx.f32 %0, %1;" : "=f"(y) : "f"(x));
    return y;
}
__device__ __forceinline__ ull ffma2(ull a, ull b, ull c) {
    ull d;
    asm("fma.rn.f32x2 %0, %1, %2, %3;" : "=l"(d) : "l"(a), "l"(b), "l"(c));
    return d;
}
__device__ __forceinline__ ull dup2(float x) {
    ull r;
    asm("mov.b64 %0, {%1, %1};" : "=l"(r) : "f"(x));
    return r;
}
__device__ __forceinline__ float2 unpack2(ull v) {
    float2 f;
    asm("mov.b64 {%0, %1}, %2;" : "=f"(f.x), "=f"(f.y) : "l"(v));
    return f;
}
__device__ __forceinline__ uint32_t to_tf32(float x) {
    uint32_t r;
    asm("cvt.rna.tf32.f32 %0, %1;" : "=r"(r) : "f"(x));
    return r;
}
__device__ __forceinline__ void mma_tf32(
    float& d0, float& d1, float& d2, float& d3,
    uint32_t a0, uint32_t a1, uint32_t a2, uint32_t a3,
    uint32_t b0, uint32_t b1)
{
    asm("mma.sync.aligned.m16n8k8.row.col.f32.tf32.tf32.f32 "
        "{%0,%1,%2,%3}, {%4,%5,%6,%7}, {%8,%9}, {%0,%1,%2,%3};"
        : "+f"(d0), "+f"(d1), "+f"(d2), "+f"(d3)
        : "r"(a0), "r"(a1), "r"(a2), "r"(a3), "r"(b0), "r"(b1));
}

#define CP16(dst_u32, src_ptr) \
    asm volatile("cp.async.ca.shared.global [%0], [%1], 16;" \
                 :: "r"(dst_u32), "l"(src_ptr))
#define CP_COMMIT()  asm volatile("cp.async.commit_group;")
#define CP_WAIT2()   asm volatile("cp.async.wait_group 2;")

// proj smem geometry: 4 stages x 2 operands x [64 rows][36 floats (pad)]
#define PROJ_PAD   36
#define PROJ_STAGE (64 * PROJ_PAD)
#define PROJ_SMEM_BYTES (4 * 2 * PROJ_STAGE * 4)   // 73728

// ---------------------------------------------------------------------------
// 1) Projection GEMM (EXACT R16 — tf32 mma + cp.async 4-stage).
// ---------------------------------------------------------------------------
__global__ __launch_bounds__(256) void proj_kernel(
    const float* __restrict__ query, const float* __restrict__ key,
    const float* __restrict__ Wq,    const float* __restrict__ Wk,
    const void*  __restrict__ vl)
{
    const long long* l = (const long long*)vl;
    const int*       w = (const int*)vl;
    bool ok64 = true;
    #pragma unroll
    for (int i = 0; i < B; i++) {
        long long x = l[i];
        if (x < 1 || x > LK) ok64 = false;
    }
    if (blockIdx.x == 0 && blockIdx.y == 0 && threadIdx.x == 0) {
        #pragma unroll
        for (int i = 0; i < B; i++) g_vlen[i] = ok64 ? (int)l[i] : w[i];
    }

    int mg = blockIdx.x * 64;
    int n0 = blockIdx.y * 64;
    bool is_q = (mg < B * LQ);

    const float *X, *W;
    float* Y;
    int m0;
    if (is_q) { X = query; W = Wq; Y = g_qp; m0 = mg; }
    else {
        m0 = mg - B * LQ;
        int bb = m0 >> 10;
        int krow = m0 & 1023;
        int vb = ok64 ? (int)l[bb] : w[bb];
        if (krow >= vb) return;
        X = key; W = Wk; Y = g_kp;
    }

    extern __shared__ float smem[];
    float* Xs = smem;
    float* Ws = smem + 4 * PROJ_STAGE;

    int tid  = threadIdx.x;
    int lane = tid & 31;
    int wf   = tid >> 5;
    int warpM = wf >> 2;
    int warpN = wf & 3;
    int g  = lane >> 2;
    int t4 = lane & 3;

    int c1 = tid, c2 = tid + 256;
    int r1 = c1 >> 3, kq1 = (c1 & 7) * 4;
    int r2 = c2 >> 3, kq2 = (c2 & 7) * 4;

    uint32_t xs_base = (uint32_t)__cvta_generic_to_shared(Xs);
    uint32_t ws_base = (uint32_t)__cvta_generic_to_shared(Ws);

    auto issue_tile = [&](int kt, int st) {
        uint32_t xb = xs_base + (uint32_t)(st * PROJ_STAGE) * 4;
        uint32_t wb = ws_base + (uint32_t)(st * PROJ_STAGE) * 4;
        CP16(xb + (uint32_t)(r1 * PROJ_PAD + kq1) * 4,
             X + (size_t)(m0 + r1) * D + kt * 32 + kq1);
        CP16(xb + (uint32_t)(r2 * PROJ_PAD + kq2) * 4,
             X + (size_t)(m0 + r2) * D + kt * 32 + kq2);
        CP16(wb + (uint32_t)(r1 * PROJ_PAD + kq1) * 4,
             W + (size_t)(n0 + r1) * D + kt * 32 + kq1);
        CP16(wb + (uint32_t)(r2 * PROJ_PAD + kq2) * 4,
             W + (size_t)(n0 + r2) * D + kt * 32 + kq2);
    };

    const int NT = D / 32;
    issue_tile(0, 0); CP_COMMIT();
    issue_tile(1, 1); CP_COMMIT();
    issue_tile(2, 2); CP_COMMIT();

    float acc[2][2][4] = {};

    int rb0 = warpM * 32;
    int cb0 = warpN * 16;

    for (int t = 0; t < NT; t++) {
        CP_WAIT2();
        __syncthreads();

        const float* xst = Xs + (t & 3) * PROJ_STAGE;
        const float* wst = Ws + (t & 3) * PROJ_STAGE;

        #pragma unroll
        for (int c = 0; c < 4; c++) {
            int kc = c * 8;
            uint32_t a[2][4], bfr[2][2];
            #pragma unroll
            for (int fi = 0; fi < 2; fi++) {
                int rb = rb0 + fi * 16;
                a[fi][0] = to_tf32(xst[(rb + g)     * PROJ_PAD + kc + t4]);
                a[fi][1] = to_tf32(xst[(rb + g + 8) * PROJ_PAD + kc + t4]);
                a[fi][2] = to_tf32(xst[(rb + g)     * PROJ_PAD + kc + t4 + 4]);
                a[fi][3] = to_tf32(xst[(rb + g + 8) * PROJ_PAD + kc + t4 + 4]);
            }
            #pragma unroll
            for (int ni = 0; ni < 2; ni++) {
                int cb = cb0 + ni * 8 + g;
                bfr[ni][0] = to_tf32(wst[cb * PROJ_PAD + kc + t4]);
                bfr[ni][1] = to_tf32(wst[cb * PROJ_PAD + kc + t4 + 4]);
            }
            #pragma unroll
            for (int fi = 0; fi < 2; fi++)
                #pragma unroll
                for (int ni = 0; ni < 2; ni++)
                    mma_tf32(acc[fi][ni][0], acc[fi][ni][1],
                             acc[fi][ni][2], acc[fi][ni][3],
                             a[fi][0], a[fi][1], a[fi][2], a[fi][3],
                             bfr[ni][0], bfr[ni][1]);
        }

        if (t + 3 < NT) issue_tile(t + 3, (t + 3) & 3);
        CP_COMMIT();
    }

    #pragma unroll
    for (int fi = 0; fi < 2; fi++) {
        #pragma unroll
        for (int ni = 0; ni < 2; ni++) {
            int row = m0 + rb0 + fi * 16 + g;
            int col = n0 + cb0 + ni * 8 + 2 * t4;
            *(float2*)(Y + (size_t)row * UNITS + col) =
                make_float2(acc[fi][ni][0], acc[fi][ni][1]);
            *(float2*)(Y + (size_t)(row + 8) * UNITS + col) =
                make_float2(acc[fi][ni][2], acc[fi][ni][3]);
        }
    }
}

// ---------------------------------------------------------------------------
// 2) Scores: warp per k, 8 q-rows, prefetch + butterfly reduce.
//    k-tile 64 -> qp preload amortized 2x; grid (16,16,4) = 1024 CTAs.
// ---------------------------------------------------------------------------
__global__ __launch_bounds__(256) void score_kernel(const float* __restrict__ vvec)
{
    int b    = blockIdx.z;
    int q0   = blockIdx.y * 8;
    int k0   = blockIdx.x * 64;
    int vlen = g_vlen[b];
    if (k0 >= vlen) return;
    int kmax = min(k0 + 64, vlen);

    int lane = threadIdx.x & 31;
    int wid  = threadIdx.x >> 5;

    int k = k0 + wid;
    if (k >= kmax) return;

    float vr[8];
    {
        float4 a = *(const float4*)(vvec + lane * 8);
        float4 c = *(const float4*)(vvec + lane * 8 + 4);
        vr[0] = a.x; vr[1] = a.y; vr[2] = a.z; vr[3] = a.w;
        vr[4] = c.x; vr[5] = c.y; vr[6] = c.z; vr[7] = c.w;
    }
    float qv[8][8];
    #pragma unroll
    for (int qq = 0; qq < 8; qq++) {
        const float* qr = g_qp + (size_t)(b * LQ + q0 + qq) * UNITS + lane * 8;
        float4 a = *(const float4*)qr;
        float4 c = *(const float4*)(qr + 4);
        qv[qq][0] = a.x; qv[qq][1] = a.y; qv[qq][2] = a.z; qv[qq][3] = a.w;
        qv[qq][4] = c.x; qv[qq][5] = c.y; qv[qq][6] = c.z; qv[qq][7] = c.w;
    }

    const float* kpb = g_kp + (size_t)b * LK * UNITS;
    float*       scb = g_sc + (size_t)(b * LQ + q0) * LK;

    int qq_out = 4 * ((lane >> 2) & 1) + 2 * ((lane >> 3) & 1) + ((lane >> 4) & 1);
    bool writer = (lane & 3) == 0;
    float* wptr = scb + (size_t)qq_out * LK;

    float4 ka, kb;
    {
        const float* kr = kpb + (size_t)k * UNITS + lane * 8;
        ka = *(const float4*)kr;
        kb = *(const float4*)(kr + 4);
    }

    while (k < kmax) {
        int kn = k + 8;
        float4 kan, kbn;
        if (kn < kmax) {
            const float* krn = kpb + (size_t)kn * UNITS + lane * 8;
            kan = *(const float4*)krn;
            kbn = *(const float4*)(krn + 4);
        }

        float kv[8] = {ka.x, ka.y, ka.z, ka.w, kb.x, kb.y, kb.z, kb.w};
        float s[8] = {0.f, 0.f, 0.f, 0.f, 0.f, 0.f, 0.f, 0.f};
        #pragma unroll
        for (int j = 0; j < 8; j++) {
            float kj = kv[j];
            float vj = vr[j];
            #pragma unroll
            for (int qq = 0; qq < 8; qq++)
                s[qq] = fmaf(vj, tanh_fast(qv[qq][j] + kj), s[qq]);
        }

        #define FOLD(dst, a0_, b0_, m)                                   \
            {                                                            \
                float x_ = (lane & (m)) ? (b0_) : (a0_);                 \
                float y_ = (lane & (m)) ? (a0_) : (b0_);                 \
                dst = x_ + __shfl_xor_sync(0xFFFFFFFFu, y_, (m));        \
            }
        float t0, t1, t2, t3, u0, u1, v;
        FOLD(t0, s[0], s[1], 16)
        FOLD(t1, s[2], s[3], 16)
        FOLD(t2, s[4], s[5], 16)
        FOLD(t3, s[6], s[7], 16)
        FOLD(u0, t0, t1, 8)
        FOLD(u1, t2, t3, 8)
        FOLD(v,  u0, u1, 4)
        v += __shfl_xor_sync(0xFFFFFFFFu, v, 2);
        v += __shfl_xor_sync(0xFFFFFFFFu, v, 1);
        #undef FOLD

        if (writer) wptr[k] = v;

        ka = kan; kb = kbn;
        k = kn;
    }
}

// ---------------------------------------------------------------------------
// 3) Fused softmax + output GEMM v2: 16q x 64v tiles (grid 8x8x4 = 256),
//    cp.async 4-stage pipeline for V, register-prefetched scores, exp
//    staged into As, ONE barrier per 32-k tile (proj's proven schedule).
// ---------------------------------------------------------------------------
__global__ __launch_bounds__(256) void out_kernel(
    const float* __restrict__ value, float* __restrict__ out)
{
    __shared__ float As[2][32][18];      // p^T tile [k][m(16)+pad]
    __shared__ float Bs[4][32][64];      // V stages (32 KB)
    __shared__ float rmax[16], rinv[16];

    int b    = blockIdx.z;
    int m0   = blockIdx.x * 16;
    int n0   = blockIdx.y * 64;
    int vlen = g_vlen[b];
    int NTk  = (vlen + 31) >> 5;         // # 32-k tiles

    const float* S = g_sc  + (size_t)(b * LQ + m0) * LK;
    const float* V = value + (size_t)b * LK * DV;

    int tid  = threadIdx.x;
    int lane = tid & 31;
    int wid  = tid >> 5;

    // phase 1: per-row max & inv-sum over [0, vlen)
    for (int r = wid; r < 16; r += 8) {
        const float* srow = S + (size_t)r * LK;
        float m = -3.0e38f;
        for (int k = lane; k < vlen; k += 32) m = fmaxf(m, srow[k]);
        #pragma unroll
        for (int off = 16; off > 0; off >>= 1)
            m = fmaxf(m, __shfl_xor_sync(0xFFFFFFFFu, m, off));
        float s = 0.f;
        for (int k = lane; k < vlen; k += 32) s += __expf(srow[k] - m);
        #pragma unroll
        for (int off = 16; off > 0; off >>= 1)
            s += __shfl_xor_sync(0xFFFFFFFFu, s, off);
        if (lane == 0) { rmax[r] = m; rinv[r] = 1.0f / s; }
    }
    __syncthreads();

    // cp.async V chunk mapping: 512 chunks/tile, 2/thread
    uint32_t bs_base = (uint32_t)__cvta_generic_to_shared(&Bs[0][0][0]);
    int c1 = tid, c2 = tid + 256;
    int vr1 = c1 >> 4, vq1 = (c1 & 15) * 4;
    int vr2 = c2 >> 4, vq2 = (c2 & 15) * 4;

    auto issue_v = [&](int kt, int st) {
        uint32_t bb = bs_base + (uint32_t)(st * 32 * 64) * 4;
        CP16(bb + (uint32_t)(vr1 * 64 + vq1) * 4,
             V + (size_t)(kt * 32 + vr1) * DV + n0 + vq1);
        CP16(bb + (uint32_t)(vr2 * 64 + vq2) * 4,
             V + (size_t)(kt * 32 + vr2) * DV + n0 + vq2);
    };

    if (0 < NTk) issue_v(0, 0);
    CP_COMMIT();
    if (1 < NTk) issue_v(1, 1);
    CP_COMMIT();
    if (2 < NTk) issue_v(2, 2);
    CP_COMMIT();

    // score staging mapping: thread owns float2 of row am at k-pair ak2
    int am  = tid >> 4;                  // 0..15
    int ak2 = (tid & 15) * 2;            // 0..30
    float mr = rmax[am];

    // prefetch scores for tile 0
    float2 srv = *(const float2*)(S + (size_t)am * LK + ak2);

    int ty = tid >> 4;                   // output row 0..15
    int tx = tid & 15;                   // output col-quad 0..15

    ull acc[2] = {0, 0};

    for (int t = 0; t < NTk; t++) {
        // stage As[t&1] from srv (exp + mask)
        {
            int kg = t * 32 + ak2;
            As[t & 1][ak2][am]     = (kg     < vlen) ? __expf(srv.x - mr) : 0.f;
            As[t & 1][ak2 + 1][am] = (kg + 1 < vlen) ? __expf(srv.y - mr) : 0.f;
        }
        CP_WAIT2();
        __syncthreads();

        // prefetch scores for tile t+1
        if (t + 1 < NTk)
            srv = *(const float2*)(S + (size_t)am * LK + (t + 1) * 32 + ak2);

        const float (*bst)[64] = Bs[t & 3];
        const float (*ast)[18] = As[t & 1];

        #pragma unroll
        for (int kk = 0; kk < 32; kk++) {
            ull ap = dup2(ast[kk][ty]);
            longlong2 bv = *(const longlong2*)&bst[kk][tx * 4];
            acc[0] = ffma2(ap, (ull)bv.x, acc[0]);
            acc[1] = ffma2(ap, (ull)bv.y, acc[1]);
        }

        if (t + 3 < NTk) issue_v(t + 3, (t + 3) & 3);
        CP_COMMIT();
        __syncthreads();                 // As[t&1] reuse needs all readers done
    }

    float inv = rinv[ty];
    float2 r0 = unpack2(acc[0]);
    float2 r1 = unpack2(acc[1]);
    *(float4*)(out + (size_t)(b * LQ + m0 + ty) * DV + n0 + tx * 4) =
        make_float4(r0.x * inv, r0.y * inv, r1.x * inv, r1.y * inv);
}

// ---------------------------------------------------------------------------
// kernel_launch — inputs: query, key, value, valid_len, W_q, W_k, v
// ---------------------------------------------------------------------------
extern "C" void kernel_launch(void* const* d_in, const int* in_sizes, int n_in,
                              void* d_out, int out_size)
{
    const float* query = (const float*)d_in[0];
    const float* key   = (const float*)d_in[1];
    const float* value = (const float*)d_in[2];
    const void*  vlen  = d_in[3];
    const float* W_q   = (const float*)d_in[4];
    const float* W_k   = (const float*)d_in[5];
    const float* vvec  = (const float*)d_in[6];
    float* out = (float*)d_out;

    cudaFuncSetAttribute(proj_kernel,
                         cudaFuncAttributeMaxDynamicSharedMemorySize,
                         PROJ_SMEM_BYTES);

    // 1) fused q+k projection via tf32 mma + cp.async: 288 CTAs
    proj_kernel<<<dim3((B * LQ + B * LK) / 64, UNITS / 64), 256,
                  PROJ_SMEM_BYTES>>>(query, key, W_q, W_k, vlen);

    // 2) scores: 16 x 16 x 4 = 1024 CTAs (masked tiles exit)
    score_kernel<<<dim3(LK / 64, LQ / 8, B), 256>>>(vvec);

    // 3) fused softmax + output GEMM: 8 x 8 x 4 = 256 CTAs, cp.async V
    out_kernel<<<dim3(LQ / 16, DV / 64, B), 256>>>(value, out);
}